// round 14
// baseline (speedup 1.0000x reference)
#include <cuda_runtime.h>
#include <cuda_bf16.h>
#include <cstdint>

// Problem constants (fixed shapes from reference)
#define BQ    16
#define KMAX  4096
#define DKD   512
#define AA    512
#define DV    512
#define MTOT  (BQ * KMAX)      // 65536 rows
#define EPSC  1e-10f

// -------- scratch (device globals; no allocation allowed) --------
__device__ float g_p[MTOT];        // p_choose
__device__ float g_l1[MTOT];       // log(clip(1-p))
__device__ float g_aw[MTOT];       // attention weights
__device__ float g_q[BQ * AA];     // query projection
__device__ float g_vw[AA];         // weight-normed v
__device__ int   g_kcut[BQ];       // per-batch effective aw length

// ============================================================
// helpers (family-generic PTX only)
// ============================================================
__device__ __forceinline__ float tanh_ap(float x) {
    float y; asm("tanh.approx.f32 %0, %1;" : "=f"(y) : "f"(x)); return y;
}
__device__ __forceinline__ uint32_t bf2(float x, float y) {
    __nv_bfloat162 h = __floats2bfloat162_rn(x, y);   // low = x, high = y
    return *reinterpret_cast<uint32_t*>(&h);
}
// m16n8k16 bf16 MMA (sm_80+), fp32 accumulate
__device__ __forceinline__ void mma16(float* c, const uint32_t* a, const uint32_t* b) {
    asm volatile(
        "mma.sync.aligned.m16n8k16.row.col.f32.bf16.bf16.f32 "
        "{%0,%1,%2,%3}, {%4,%5,%6,%7}, {%8,%9}, {%0,%1,%2,%3};"
        : "+f"(c[0]), "+f"(c[1]), "+f"(c[2]), "+f"(c[3])
        : "r"(a[0]), "r"(a[1]), "r"(a[2]), "r"(a[3]), "r"(b[0]), "r"(b[1]));
}

// ============================================================
// Kernel 0: v_w = v_g * v_v / ||v_v||
// ============================================================
__global__ void k_vw(const float* __restrict__ vv, const float* __restrict__ vg) {
    __shared__ float red[16];
    int t = threadIdx.x;          // 512 threads
    float v = vv[t];
    float s = v * v;
    #pragma unroll
    for (int o = 16; o; o >>= 1) s += __shfl_xor_sync(~0u, s, o);
    if ((t & 31) == 0) red[t >> 5] = s;
    __syncthreads();
    if (t < 32) {
        float x = (t < 16) ? red[t] : 0.f;
        #pragma unroll
        for (int o = 8; o; o >>= 1) x += __shfl_xor_sync(~0u, x, o);
        if (t == 0) red[0] = x;
    }
    __syncthreads();
    float inv_norm = rsqrtf(red[0]);
    g_vw[t] = vg[0] * v * inv_norm;
}

// ============================================================
// Kernel 1: q_proj[b][a] = query[b,:] . wq_w[a,:]
// ============================================================
__global__ void k_q(const float* __restrict__ query, const float* __restrict__ wq) {
    int b = blockIdx.x;
    int warp = threadIdx.x >> 5, lane = threadIdx.x & 31;
    int a = blockIdx.y * 8 + warp;
    const float* qr = query + (size_t)b * DKD;
    const float* wr = wq + (size_t)a * DKD;
    float s = 0.f;
    for (int d = lane; d < DKD; d += 32) s += qr[d] * wr[d];
    #pragma unroll
    for (int o = 16; o; o >>= 1) s += __shfl_xor_sync(~0u, s, o);
    if (lane == 0) g_q[b * AA + a] = s;
}

// ============================================================
// Kernel 2: bf16 mma.sync GEMM + fused tanh/vw/sigmoid epilogue
//   (identical to R13 — measured at the legacy-HMMA floor)
// ============================================================
#define STG_BYTES 16384            // A 128x32 bf16 (8KB) + B 128x32 bf16 (8KB)
#define NSTAGE    3
#define DYN_BYTES (NSTAGE * STG_BYTES)   // 49152

__global__ __launch_bounds__(256, 2)
void k_main(const float* __restrict__ key, const float* __restrict__ wk,
            const float* __restrict__ wkb, const float* __restrict__ noise,
            const float* __restrict__ rr)
{
    extern __shared__ char smc[];          // 3 stages
    __shared__ float cb[512], vs[512], red[128];

    const int tid  = threadIdx.x;
    const int lane = tid & 31;
    const int wid  = tid >> 5;
    const int wm   = wid >> 1;        // 0..3 (M, 32 rows each)
    const int wn   = wid & 1;         // 0..1 (N, 64 cols each)
    const int g    = lane >> 2;       // 0..7
    const int t4   = lane & 3;        // 0..3
    const int m0   = blockIdx.x * 128;
    const int b    = blockIdx.x >> 5; // 32 M-tiles per batch

    for (int i = tid; i < 512; i += 256) {
        cb[i] = wkb[i] + g_q[b * AA + i];
        vs[i] = g_vw[i];
    }
    __syncthreads();

    const int lr  = tid >> 3;         // 0..31 (row group)
    const int lc4 = tid & 7;          // 0..7  (float4 col = 8B bf16 slot)
    const uint32_t dcol = (uint32_t)(lc4 ^ (lr & 7)) * 8;

    uint2 pk[8];
    auto ldgcvt = [&](int cc) {
        const int kk = (cc & 15) * 32;
        const float* Ag = key + (size_t)(m0 + lr) * DKD + kk + lc4 * 4;
        #pragma unroll
        for (int it = 0; it < 4; ++it) {
            float4 v = *reinterpret_cast<const float4*>(Ag + (size_t)(it * 32) * DKD);
            pk[it] = make_uint2(bf2(v.x, v.y), bf2(v.z, v.w));
        }
        const int n0 = (cc >> 4) * 128;
        const float* Bg = wk + (size_t)(n0 + lr) * DKD + kk + lc4 * 4;
        #pragma unroll
        for (int it = 0; it < 4; ++it) {
            float4 v = *reinterpret_cast<const float4*>(Bg + (size_t)(it * 32) * DKD);
            pk[4 + it] = make_uint2(bf2(v.x, v.y), bf2(v.z, v.w));
        }
    };
    auto sts = [&](int cc) {
        char* st = smc + (cc % NSTAGE) * STG_BYTES;
        #pragma unroll
        for (int it = 0; it < 4; ++it)
            *reinterpret_cast<uint2*>(st + (lr + it * 32) * 64 + dcol) = pk[it];
        #pragma unroll
        for (int it = 0; it < 4; ++it)
            *reinterpret_cast<uint2*>(st + 8192 + (lr + it * 32) * 64 + dcol) = pk[4 + it];
    };

    float ep[4] = {0.f, 0.f, 0.f, 0.f};
    float C[2][8][4];
    #pragma unroll
    for (int im = 0; im < 2; im++)
        #pragma unroll
        for (int jn = 0; jn < 8; jn++)
            #pragma unroll
            for (int r = 0; r < 4; r++) C[im][jn][r] = 0.f;

    ldgcvt(0);
    for (int cc = 0; cc < 64; ++cc) {
        sts(cc);
        __syncthreads();
        if (cc < 63) ldgcvt(cc + 1);

        const char* stg = smc + (cc % NSTAGE) * STG_BYTES;
        #pragma unroll
        for (int ks = 0; ks < 2; ++ks) {
            const int sb0 = ks * 4 + (t4 >> 1);
            const int o0 = (((sb0    ) ^ g) << 3) | ((t4 & 1) << 2);
            const int o1 = (((sb0 + 2) ^ g) << 3) | ((t4 & 1) << 2);
            uint32_t afr[2][4];
            #pragma unroll
            for (int im = 0; im < 2; ++im) {
                const char* p = stg + (wm * 32 + im * 16 + g) * 64;
                afr[im][0] = *reinterpret_cast<const uint32_t*>(p + o0);
                afr[im][1] = *reinterpret_cast<const uint32_t*>(p + 512 + o0); // +8 rows
                afr[im][2] = *reinterpret_cast<const uint32_t*>(p + o1);
                afr[im][3] = *reinterpret_cast<const uint32_t*>(p + 512 + o1);
            }
            #pragma unroll
            for (int jn = 0; jn < 8; ++jn) {
                const char* p = stg + 8192 + (wn * 64 + jn * 8 + g) * 64;
                uint32_t bfr[2];
                bfr[0] = *reinterpret_cast<const uint32_t*>(p + o0);
                bfr[1] = *reinterpret_cast<const uint32_t*>(p + o1);
                mma16(C[0][jn], afr[0], bfr);
                mma16(C[1][jn], afr[1], bfr);
            }
        }

        if ((cc & 15) == 15) {
            // epilogue for finished n-chunk: tanh(C + cb) . vs
            const int n0 = (cc >> 4) * 128;
            #pragma unroll
            for (int im = 0; im < 2; ++im)
                #pragma unroll
                for (int jn = 0; jn < 8; ++jn)
                    #pragma unroll
                    for (int r = 0; r < 4; ++r) {
                        const int col = n0 + wn * 64 + jn * 8 + t4 * 2 + (r & 1);
                        const float x = C[im][jn][r] + cb[col];
                        ep[im * 2 + (r >> 1)] += tanh_ap(x) * vs[col];
                        C[im][jn][r] = 0.f;
                    }
        }
    }

    // reduce over the 4 k-lanes (t4), then combine the 2 N-warps
    #pragma unroll
    for (int i = 0; i < 4; ++i) {
        ep[i] += __shfl_xor_sync(~0u, ep[i], 1);
        ep[i] += __shfl_xor_sync(~0u, ep[i], 2);
    }
    __syncthreads();
    if (t4 == 0 && wn == 0) {
        #pragma unroll
        for (int i = 0; i < 4; ++i)
            red[wm * 32 + (i >> 1) * 16 + (i & 1) * 8 + g] = ep[i];
    }
    __syncthreads();
    if (t4 == 0 && wn == 1) {
        #pragma unroll
        for (int i = 0; i < 4; ++i)
            red[wm * 32 + (i >> 1) * 16 + (i & 1) * 8 + g] += ep[i];
    }
    __syncthreads();

    if (tid < 128) {
        const int m = m0 + tid;
        const float e = red[tid] + rr[0] + noise[m];
        const float pp = 1.f / (1.f + expf(-e));
        g_p[m] = pp;
        g_l1[m] = logf(fminf(fmaxf(1.f - pp, EPSC), 1.f));
    }
}

// ============================================================
// Kernel 3: per-batch scan + aw output + zero cv region
//   aw[k] = p[k] * exp(S_k), S_k = 1 + sum_{i<k} l1[i].
//   S is non-increasing (l1<=0) after k=0, so beyond the first k
//   with S < -34 every aw is < 2e-15 -> compute per-batch cutoff
//   K_b = #{k : S_k >= -34} for k_cv (exact & input-adaptive).
// ============================================================
__global__ void k_scan(float* __restrict__ out) {
    __shared__ float ws[512];
    __shared__ int   cnt[16];
    const int b = blockIdx.x, t = threadIdx.x;     // 512 threads x 8 elems
    const float* l1 = g_l1 + b * KMAX;
    const float* p  = g_p  + b * KMAX;

    float loc[8];
    float s = 0.f;
    const int base = t * 8;
    #pragma unroll
    for (int i = 0; i < 8; i++) {
        int idx = base + i;
        float x = (idx == 0) ? 1.0f : l1[idx - 1];
        s += x;
        loc[i] = s;              // inclusive within thread
    }
    ws[t] = s;
    __syncthreads();
    for (int off = 1; off < 512; off <<= 1) {
        float v = (t >= off) ? ws[t - off] : 0.f;
        __syncthreads();
        ws[t] += v;
        __syncthreads();
    }
    float pre = (t == 0) ? 0.f : ws[t - 1];

    float* aw = g_aw + b * KMAX;
    float* awo = out + BQ * DV + b * KMAX;
    int live = 0;
    #pragma unroll
    for (int i = 0; i < 8; i++) {
        int idx = base + i;
        float ex = pre + loc[i];
        float v = p[idx] * __expf(ex);
        aw[idx] = v;
        awo[idx] = v;
        live += (ex >= -34.f) ? 1 : 0;
    }
    out[b * DV + t] = 0.f;   // zero cv region (accumulated by k_cv)

    // reduce 'live' counts -> per-batch cutoff (S monotone => count = index)
    #pragma unroll
    for (int o = 16; o; o >>= 1) live += __shfl_xor_sync(~0u, live, o);
    if ((t & 31) == 0) cnt[t >> 5] = live;
    __syncthreads();
    if (t < 16) {
        int x = cnt[t];
        #pragma unroll
        for (int o = 8; o; o >>= 1) x += __shfl_xor_sync(0xFFFFu, x, o);
        if (t == 0) g_kcut[b] = x;
    }
}

// ============================================================
// Kernel 4: cv[b][v] = sum_k aw[b,k] * value[b,k,v]
//   Blocks whose k-slice starts beyond the batch cutoff exit.
//   128 threads x float4 over V; aw slice staged in SMEM.
// ============================================================
__global__ void k_cv(const float* __restrict__ value, float* __restrict__ out) {
    __shared__ float saw[256];
    const int b = blockIdx.x, ks = blockIdx.y;
    if (ks * 256 >= g_kcut[b]) return;       // aw ~ 0 beyond cutoff
    const int t = threadIdx.x;               // 128 threads
    saw[t] = g_aw[b * KMAX + ks * 256 + t];
    saw[t + 128] = g_aw[b * KMAX + ks * 256 + t + 128];
    __syncthreads();
    const float* val = value + ((size_t)b * KMAX + (size_t)ks * 256) * DV + t * 4;
    float4 acc = make_float4(0.f, 0.f, 0.f, 0.f);
    #pragma unroll 4
    for (int k = 0; k < 256; k++) {
        const float a = saw[k];
        const float4 v = *reinterpret_cast<const float4*>(val + (size_t)k * DV);
        acc.x += a * v.x; acc.y += a * v.y; acc.z += a * v.z; acc.w += a * v.w;
    }
    float* o = out + b * DV + t * 4;
    atomicAdd(o + 0, acc.x);
    atomicAdd(o + 1, acc.y);
    atomicAdd(o + 2, acc.z);
    atomicAdd(o + 3, acc.w);
}

extern "C" void kernel_launch(void* const* d_in, const int* in_sizes, int n_in,
                              void* d_out, int out_size) {
    const float* key   = (const float*)d_in[0];  // [B,KMAX,DK]
    const float* value = (const float*)d_in[1];  // [B,KMAX,DV]
    const float* query = (const float*)d_in[2];  // [B,1,DQ]
    const float* noise = (const float*)d_in[3];  // [B,KMAX]
    const float* wkw   = (const float*)d_in[4];  // [A,DK]
    const float* wkb   = (const float*)d_in[5];  // [A]
    const float* wqw   = (const float*)d_in[6];  // [A,DQ]
    const float* vv    = (const float*)d_in[7];  // [1,A]
    const float* vg    = (const float*)d_in[8];  // [1]
    const float* r     = (const float*)d_in[9];  // [1]
    float* out = (float*)d_out;                  // cv [B,1,DV] then aw [B,KMAX,1]

    cudaFuncSetAttribute(k_main, cudaFuncAttributeMaxDynamicSharedMemorySize, DYN_BYTES);

    k_vw<<<1, 512>>>(vv, vg);
    k_q<<<dim3(BQ, 64), 256>>>(query, wqw);
    k_main<<<MTOT / 128, 256, DYN_BYTES>>>(key, wkw, wkb, noise, r);
    k_scan<<<BQ, 512>>>(out);
    k_cv<<<dim3(BQ, 16), 128>>>(value, out);
}

// round 15
// speedup vs baseline: 1.0802x; 1.0802x over previous
#include <cuda_runtime.h>
#include <cuda_bf16.h>
#include <cstdint>

// Problem constants (fixed shapes from reference)
#define BQ    16
#define KMAX  4096
#define DKD   512
#define AA    512
#define DV    512
#define MTOT  (BQ * KMAX)      // 65536 rows
#define EPSC  1e-10f

// -------- scratch (device globals; no allocation allowed) --------
__device__ float g_p[MTOT];        // p_choose
__device__ float g_l1[MTOT];       // log(clip(1-p))
__device__ float g_aw[MTOT];       // attention weights
__device__ float g_q[BQ * AA];     // query projection
__device__ float g_vw[AA];         // weight-normed v
__device__ int   g_kcut[BQ];       // per-batch effective aw length

// ============================================================
// helpers (family-generic PTX only)
// ============================================================
__device__ __forceinline__ float tanh_ap(float x) {
    float y; asm("tanh.approx.f32 %0, %1;" : "=f"(y) : "f"(x)); return y;
}
__device__ __forceinline__ uint32_t bf2(float x, float y) {
    __nv_bfloat162 h = __floats2bfloat162_rn(x, y);   // low = x, high = y
    return *reinterpret_cast<uint32_t*>(&h);
}
// m16n8k16 bf16 MMA (sm_80+), fp32 accumulate
__device__ __forceinline__ void mma16(float* c, const uint32_t* a, const uint32_t* b) {
    asm volatile(
        "mma.sync.aligned.m16n8k16.row.col.f32.bf16.bf16.f32 "
        "{%0,%1,%2,%3}, {%4,%5,%6,%7}, {%8,%9}, {%0,%1,%2,%3};"
        : "+f"(c[0]), "+f"(c[1]), "+f"(c[2]), "+f"(c[3])
        : "r"(a[0]), "r"(a[1]), "r"(a[2]), "r"(a[3]), "r"(b[0]), "r"(b[1]));
}

// ============================================================
// Kernel 0: v_w = v_g * v_v / ||v_v||
// ============================================================
__global__ void k_vw(const float* __restrict__ vv, const float* __restrict__ vg) {
    __shared__ float red[16];
    int t = threadIdx.x;          // 512 threads
    float v = vv[t];
    float s = v * v;
    #pragma unroll
    for (int o = 16; o; o >>= 1) s += __shfl_xor_sync(~0u, s, o);
    if ((t & 31) == 0) red[t >> 5] = s;
    __syncthreads();
    if (t < 32) {
        float x = (t < 16) ? red[t] : 0.f;
        #pragma unroll
        for (int o = 8; o; o >>= 1) x += __shfl_xor_sync(~0u, x, o);
        if (t == 0) red[0] = x;
    }
    __syncthreads();
    float inv_norm = rsqrtf(red[0]);
    g_vw[t] = vg[0] * v * inv_norm;
}

// ============================================================
// Kernel 1: q_proj[b][a] = query[b,:] . wq_w[a,:]
// ============================================================
__global__ void k_q(const float* __restrict__ query, const float* __restrict__ wq) {
    int b = blockIdx.x;
    int warp = threadIdx.x >> 5, lane = threadIdx.x & 31;
    int a = blockIdx.y * 8 + warp;
    const float* qr = query + (size_t)b * DKD;
    const float* wr = wq + (size_t)a * DKD;
    float s = 0.f;
    for (int d = lane; d < DKD; d += 32) s += qr[d] * wr[d];
    #pragma unroll
    for (int o = 16; o; o >>= 1) s += __shfl_xor_sync(~0u, s, o);
    if (lane == 0) g_q[b * AA + a] = s;
}

// ============================================================
// Kernel 2: bf16 mma.sync GEMM + fused tanh/vw/sigmoid epilogue
//   (byte-identical to R13 — measured at the legacy-HMMA floor)
// ============================================================
#define STG_BYTES 16384            // A 128x32 bf16 (8KB) + B 128x32 bf16 (8KB)
#define NSTAGE    3
#define DYN_BYTES (NSTAGE * STG_BYTES)   // 49152

__global__ __launch_bounds__(256, 2)
void k_main(const float* __restrict__ key, const float* __restrict__ wk,
            const float* __restrict__ wkb, const float* __restrict__ noise,
            const float* __restrict__ rr)
{
    extern __shared__ char smc[];          // 3 stages
    __shared__ float cb[512], vs[512], red[128];

    const int tid  = threadIdx.x;
    const int lane = tid & 31;
    const int wid  = tid >> 5;
    const int wm   = wid >> 1;        // 0..3 (M, 32 rows each)
    const int wn   = wid & 1;         // 0..1 (N, 64 cols each)
    const int g    = lane >> 2;       // 0..7
    const int t4   = lane & 3;        // 0..3
    const int m0   = blockIdx.x * 128;
    const int b    = blockIdx.x >> 5; // 32 M-tiles per batch

    for (int i = tid; i < 512; i += 256) {
        cb[i] = wkb[i] + g_q[b * AA + i];
        vs[i] = g_vw[i];
    }
    __syncthreads();

    const int lr  = tid >> 3;         // 0..31 (row group)
    const int lc4 = tid & 7;          // 0..7  (float4 col = 8B bf16 slot)
    const uint32_t dcol = (uint32_t)(lc4 ^ (lr & 7)) * 8;

    uint2 pk[8];
    auto ldgcvt = [&](int cc) {
        const int kk = (cc & 15) * 32;
        const float* Ag = key + (size_t)(m0 + lr) * DKD + kk + lc4 * 4;
        #pragma unroll
        for (int it = 0; it < 4; ++it) {
            float4 v = *reinterpret_cast<const float4*>(Ag + (size_t)(it * 32) * DKD);
            pk[it] = make_uint2(bf2(v.x, v.y), bf2(v.z, v.w));
        }
        const int n0 = (cc >> 4) * 128;
        const float* Bg = wk + (size_t)(n0 + lr) * DKD + kk + lc4 * 4;
        #pragma unroll
        for (int it = 0; it < 4; ++it) {
            float4 v = *reinterpret_cast<const float4*>(Bg + (size_t)(it * 32) * DKD);
            pk[4 + it] = make_uint2(bf2(v.x, v.y), bf2(v.z, v.w));
        }
    };
    auto sts = [&](int cc) {
        char* st = smc + (cc % NSTAGE) * STG_BYTES;
        #pragma unroll
        for (int it = 0; it < 4; ++it)
            *reinterpret_cast<uint2*>(st + (lr + it * 32) * 64 + dcol) = pk[it];
        #pragma unroll
        for (int it = 0; it < 4; ++it)
            *reinterpret_cast<uint2*>(st + 8192 + (lr + it * 32) * 64 + dcol) = pk[4 + it];
    };

    float ep[4] = {0.f, 0.f, 0.f, 0.f};
    float C[2][8][4];
    #pragma unroll
    for (int im = 0; im < 2; im++)
        #pragma unroll
        for (int jn = 0; jn < 8; jn++)
            #pragma unroll
            for (int r = 0; r < 4; r++) C[im][jn][r] = 0.f;

    ldgcvt(0);
    for (int cc = 0; cc < 64; ++cc) {
        sts(cc);
        __syncthreads();
        if (cc < 63) ldgcvt(cc + 1);

        const char* stg = smc + (cc % NSTAGE) * STG_BYTES;
        #pragma unroll
        for (int ks = 0; ks < 2; ++ks) {
            const int sb0 = ks * 4 + (t4 >> 1);
            const int o0 = (((sb0    ) ^ g) << 3) | ((t4 & 1) << 2);
            const int o1 = (((sb0 + 2) ^ g) << 3) | ((t4 & 1) << 2);
            uint32_t afr[2][4];
            #pragma unroll
            for (int im = 0; im < 2; ++im) {
                const char* p = stg + (wm * 32 + im * 16 + g) * 64;
                afr[im][0] = *reinterpret_cast<const uint32_t*>(p + o0);
                afr[im][1] = *reinterpret_cast<const uint32_t*>(p + 512 + o0); // +8 rows
                afr[im][2] = *reinterpret_cast<const uint32_t*>(p + o1);
                afr[im][3] = *reinterpret_cast<const uint32_t*>(p + 512 + o1);
            }
            #pragma unroll
            for (int jn = 0; jn < 8; ++jn) {
                const char* p = stg + 8192 + (wn * 64 + jn * 8 + g) * 64;
                uint32_t bfr[2];
                bfr[0] = *reinterpret_cast<const uint32_t*>(p + o0);
                bfr[1] = *reinterpret_cast<const uint32_t*>(p + o1);
                mma16(C[0][jn], afr[0], bfr);
                mma16(C[1][jn], afr[1], bfr);
            }
        }

        if ((cc & 15) == 15) {
            // epilogue for finished n-chunk: tanh(C + cb) . vs
            const int n0 = (cc >> 4) * 128;
            #pragma unroll
            for (int im = 0; im < 2; ++im)
                #pragma unroll
                for (int jn = 0; jn < 8; ++jn)
                    #pragma unroll
                    for (int r = 0; r < 4; ++r) {
                        const int col = n0 + wn * 64 + jn * 8 + t4 * 2 + (r & 1);
                        const float x = C[im][jn][r] + cb[col];
                        ep[im * 2 + (r >> 1)] += tanh_ap(x) * vs[col];
                        C[im][jn][r] = 0.f;
                    }
        }
    }

    // reduce over the 4 k-lanes (t4), then combine the 2 N-warps
    #pragma unroll
    for (int i = 0; i < 4; ++i) {
        ep[i] += __shfl_xor_sync(~0u, ep[i], 1);
        ep[i] += __shfl_xor_sync(~0u, ep[i], 2);
    }
    __syncthreads();
    if (t4 == 0 && wn == 0) {
        #pragma unroll
        for (int i = 0; i < 4; ++i)
            red[wm * 32 + (i >> 1) * 16 + (i & 1) * 8 + g] = ep[i];
    }
    __syncthreads();
    if (t4 == 0 && wn == 1) {
        #pragma unroll
        for (int i = 0; i < 4; ++i)
            red[wm * 32 + (i >> 1) * 16 + (i & 1) * 8 + g] += ep[i];
    }
    __syncthreads();

    if (tid < 128) {
        const int m = m0 + tid;
        const float e = red[tid] + rr[0] + noise[m];
        const float pp = 1.f / (1.f + expf(-e));
        g_p[m] = pp;
        g_l1[m] = logf(fminf(fmaxf(1.f - pp, EPSC), 1.f));
    }
}

// ============================================================
// Kernel 3: per-batch scan + aw output + zero cv region
//   aw[k] = p[k] * exp(S_k), S_k = 1 + sum_{i<k} l1[i].
//   S is non-increasing after k=0 (l1<=0), so past the first k
//   with S < -20 every aw < p*e^-20 ~ 5e-11 -> contributes < 1e-9
//   rel to cv. Cutoff K_b = #{k : S_k >= -20} (exact, adaptive).
//   aw itself is still written for ALL k.
// ============================================================
__global__ void k_scan(float* __restrict__ out) {
    __shared__ float ws[512];
    __shared__ int   cnt[16];
    const int b = blockIdx.x, t = threadIdx.x;     // 512 threads x 8 elems
    const float* l1 = g_l1 + b * KMAX;
    const float* p  = g_p  + b * KMAX;

    float loc[8];
    float s = 0.f;
    const int base = t * 8;
    #pragma unroll
    for (int i = 0; i < 8; i++) {
        int idx = base + i;
        float x = (idx == 0) ? 1.0f : l1[idx - 1];
        s += x;
        loc[i] = s;              // inclusive within thread
    }
    ws[t] = s;
    __syncthreads();
    for (int off = 1; off < 512; off <<= 1) {
        float v = (t >= off) ? ws[t - off] : 0.f;
        __syncthreads();
        ws[t] += v;
        __syncthreads();
    }
    float pre = (t == 0) ? 0.f : ws[t - 1];

    float* aw = g_aw + b * KMAX;
    float* awo = out + BQ * DV + b * KMAX;
    int live = 0;
    #pragma unroll
    for (int i = 0; i < 8; i++) {
        int idx = base + i;
        float ex = pre + loc[i];
        float v = p[idx] * __expf(ex);
        aw[idx] = v;
        awo[idx] = v;
        live += (ex >= -20.f) ? 1 : 0;
    }
    out[b * DV + t] = 0.f;   // zero cv region (accumulated by k_cv)

    // reduce 'live' counts -> per-batch cutoff (S monotone => count = index)
    #pragma unroll
    for (int o = 16; o; o >>= 1) live += __shfl_xor_sync(~0u, live, o);
    if ((t & 31) == 0) cnt[t >> 5] = live;
    __syncthreads();
    if (t < 16) {
        int x = cnt[t];
        #pragma unroll
        for (int o = 8; o; o >>= 1) x += __shfl_xor_sync(0xFFFFu, x, o);
        if (t == 0) g_kcut[b] = x;
    }
}

// ============================================================
// Kernel 4: cv[b][v] = sum_k aw[b,k] * value[b,k,v]
//   R13 shape (512 thr, coalesced, 1 atomic/thread) + cutoff.
// ============================================================
__global__ void k_cv(const float* __restrict__ value, float* __restrict__ out) {
    const int b = blockIdx.x, ks = blockIdx.y;
    if (ks * 256 >= g_kcut[b]) return;       // aw ~ 0 beyond cutoff
    const int v = threadIdx.x;
    const float* aw = g_aw + b * KMAX + ks * 256;
    const float* val = value + ((size_t)b * KMAX + (size_t)ks * 256) * DV + v;
    float acc = 0.f;
    #pragma unroll 8
    for (int k = 0; k < 256; k++) acc += aw[k] * __ldg(val + (size_t)k * DV);
    atomicAdd(&out[b * DV + v], acc);
}

extern "C" void kernel_launch(void* const* d_in, const int* in_sizes, int n_in,
                              void* d_out, int out_size) {
    const float* key   = (const float*)d_in[0];  // [B,KMAX,DK]
    const float* value = (const float*)d_in[1];  // [B,KMAX,DV]
    const float* query = (const float*)d_in[2];  // [B,1,DQ]
    const float* noise = (const float*)d_in[3];  // [B,KMAX]
    const float* wkw   = (const float*)d_in[4];  // [A,DK]
    const float* wkb   = (const float*)d_in[5];  // [A]
    const float* wqw   = (const float*)d_in[6];  // [A,DQ]
    const float* vv    = (const float*)d_in[7];  // [1,A]
    const float* vg    = (const float*)d_in[8];  // [1]
    const float* r     = (const float*)d_in[9];  // [1]
    float* out = (float*)d_out;                  // cv [B,1,DV] then aw [B,KMAX,1]

    cudaFuncSetAttribute(k_main, cudaFuncAttributeMaxDynamicSharedMemorySize, DYN_BYTES);

    k_vw<<<1, 512>>>(vv, vg);
    k_q<<<dim3(BQ, 64), 256>>>(query, wqw);
    k_main<<<MTOT / 128, 256, DYN_BYTES>>>(key, wkw, wkb, noise, r);
    k_scan<<<BQ, 512>>>(out);
    k_cv<<<dim3(BQ, 16), 512>>>(value, out);
}